// round 3
// baseline (speedup 1.0000x reference)
#include <cuda_runtime.h>
#include <math.h>

#define NL 12
#define NH 16
#define NC 1024
#define NT 512
#define NB 4
#define HDIM 64
#define NF 4096
#define NV 32000
#define MROWS (NB*NT)   // 2048
#define LN_EPS 1e-5f

// ---------------- static scratch (no allocations allowed) ----------------
__device__ float g_x [MROWS*NC];
__device__ float g_xn[MROWS*NC];
__device__ float g_q [MROWS*NC];
__device__ float g_k [MROWS*NC];
__device__ float g_v [MROWS*NC];
__device__ float g_y [MROWS*NC];
__device__ float g_h [MROWS*NF];

// ---------------- embedding ----------------
__global__ void embed_kernel(const int* __restrict__ idx,
                             const float* __restrict__ tok,
                             const float* __restrict__ pos) {
    int row = blockIdx.x;            // b*NT + t
    int t   = row % NT;
    int tk  = idx[row];
    const float4* tr = (const float4*)(tok + (long)tk * NC);
    const float4* pr = (const float4*)(pos + (long)t  * NC);
    float4* xr = (float4*)(g_x + (long)row * NC);
    for (int c = threadIdx.x; c < NC / 4; c += blockDim.x) {
        float4 a = tr[c], b = pr[c];
        a.x += b.x; a.y += b.y; a.z += b.z; a.w += b.w;
        xr[c] = a;
    }
}

// ---------------- layernorm (block of 256 per row, warp-shuffle reduce) ----------------
__global__ __launch_bounds__(256)
void ln_kernel(const float* __restrict__ x,
               const float* __restrict__ gg,
               const float* __restrict__ bb,
               float* __restrict__ out) {
    __shared__ float rs[8], rs2[8];
    const int row = blockIdx.x;
    const int tid = threadIdx.x;
    const float4* xr = (const float4*)(x + (long)row * NC);
    float4* orow = (float4*)(out + (long)row * NC);

    float s = 0.f, s2 = 0.f;
    float4 vals[1];
    // NC/4 = 256 float4 elems, exactly one per thread
    float4 v = xr[tid];
    s  = v.x + v.y + v.z + v.w;
    s2 = v.x*v.x + v.y*v.y + v.z*v.z + v.w*v.w;
    vals[0] = v;

    #pragma unroll
    for (int off = 16; off > 0; off >>= 1) {
        s  += __shfl_xor_sync(0xffffffff, s,  off);
        s2 += __shfl_xor_sync(0xffffffff, s2, off);
    }
    if ((tid & 31) == 0) { rs[tid >> 5] = s; rs2[tid >> 5] = s2; }
    __syncthreads();
    if (tid < 8) { s = rs[tid]; s2 = rs2[tid]; }
    if (tid < 8) {
        #pragma unroll
        for (int off = 4; off > 0; off >>= 1) {
            s  += __shfl_xor_sync(0xff, s,  off);
            s2 += __shfl_xor_sync(0xff, s2, off);
        }
        if (tid == 0) { rs[0] = s; rs2[0] = s2; }
    }
    __syncthreads();
    float mean = rs[0] * (1.0f / NC);
    float var  = rs2[0] * (1.0f / NC) - mean * mean;
    float rstd = rsqrtf(var + LN_EPS);

    const float4* g4 = (const float4*)gg;
    const float4* b4 = (const float4*)bb;
    float4 g = g4[tid], bv = b4[tid], o;
    v = vals[0];
    o.x = (v.x - mean) * rstd * g.x + bv.x;
    o.y = (v.y - mean) * rstd * g.y + bv.y;
    o.z = (v.z - mean) * rstd * g.z + bv.z;
    o.w = (v.w - mean) * rstd * g.w + bv.w;
    orow[tid] = o;
}

// ---------------- tiled SGEMM: C = A(MxK) @ B(KxN) [+bias][+res][relu] ----------------
template<bool BIAS, bool RELU, bool RES>
__global__ __launch_bounds__(256)
void sgemm_kernel(int M, int N, int K,
                  const float* __restrict__ A,
                  const float* __restrict__ Bm,
                  const float* __restrict__ bias,
                  const float* __restrict__ res,
                  float* __restrict__ Cm) {
    const int BM = 128, BN = 128, BK = 16, TM = 8, TN = 8;
    __shared__ float As[BK][BM];
    __shared__ float Bs[BK][BN];

    const int tid = threadIdx.x;
    const int bcol = blockIdx.x, brow = blockIdx.y;

    A  += (long)brow * BM * K;
    Bm += bcol * BN;
    Cm += (long)brow * BM * N + bcol * BN;
    if (RES)  res  += (long)brow * BM * N + bcol * BN;
    if (BIAS) bias += bcol * BN;

    const int aRow  = tid / (BK / 4);          // 0..63
    const int aCol4 = (tid % (BK / 4)) * 4;    // 0,4,8,12
    const int bRow  = tid / (BN / 4);          // 0..7
    const int bCol4 = (tid % (BN / 4)) * 4;    // 0..124

    float acc[TM][TN];
    #pragma unroll
    for (int i = 0; i < TM; i++)
        #pragma unroll
        for (int j = 0; j < TN; j++) acc[i][j] = 0.f;

    float regM[TM], regN[TN];
    const int tRow = (tid / 16) * TM;
    const int tCol = (tid % 16) * TN;

    for (int k0 = 0; k0 < K; k0 += BK) {
        #pragma unroll
        for (int i = 0; i < BM; i += 64) {
            float4 v = *reinterpret_cast<const float4*>(&A[(aRow + i) * K + k0 + aCol4]);
            As[aCol4 + 0][aRow + i] = v.x;
            As[aCol4 + 1][aRow + i] = v.y;
            As[aCol4 + 2][aRow + i] = v.z;
            As[aCol4 + 3][aRow + i] = v.w;
        }
        #pragma unroll
        for (int i = 0; i < BK; i += 8) {
            float4 v = *reinterpret_cast<const float4*>(&Bm[(k0 + bRow + i) * N + bCol4]);
            *reinterpret_cast<float4*>(&Bs[bRow + i][bCol4]) = v;
        }
        __syncthreads();
        #pragma unroll
        for (int kk = 0; kk < BK; kk++) {
            #pragma unroll
            for (int i = 0; i < TM; i++) regM[i] = As[kk][tRow + i];
            #pragma unroll
            for (int j = 0; j < TN; j++) regN[j] = Bs[kk][tCol + j];
            #pragma unroll
            for (int i = 0; i < TM; i++)
                #pragma unroll
                for (int j = 0; j < TN; j++)
                    acc[i][j] += regM[i] * regN[j];
        }
        __syncthreads();
    }

    #pragma unroll
    for (int i = 0; i < TM; i++) {
        int r = tRow + i;
        #pragma unroll
        for (int j = 0; j < TN; j += 4) {
            float4 o;
            o.x = acc[i][j + 0]; o.y = acc[i][j + 1];
            o.z = acc[i][j + 2]; o.w = acc[i][j + 3];
            if (BIAS) {
                o.x += bias[tCol + j + 0]; o.y += bias[tCol + j + 1];
                o.z += bias[tCol + j + 2]; o.w += bias[tCol + j + 3];
            }
            if (RES) {
                float4 rv = *reinterpret_cast<const float4*>(&res[r * N + tCol + j]);
                o.x += rv.x; o.y += rv.y; o.z += rv.z; o.w += rv.w;
            }
            if (RELU) {
                o.x = fmaxf(o.x, 0.f); o.y = fmaxf(o.y, 0.f);
                o.z = fmaxf(o.z, 0.f); o.w = fmaxf(o.w, 0.f);
            }
            *reinterpret_cast<float4*>(&Cm[r * N + tCol + j]) = o;
        }
    }
}

// ---------------- causal attention: one block per (b,h,t) query row ----------------
__global__ __launch_bounds__(128)
void attn_kernel(const float* __restrict__ Q,
                 const float* __restrict__ K,
                 const float* __restrict__ Vv,
                 float* __restrict__ Y) {
    __shared__ float qs[HDIM];
    __shared__ float ks[128][HDIM + 1];
    __shared__ float sc[NT];
    __shared__ float red[128];
    __shared__ float part[2][HDIM];

    const int t = blockIdx.x, h = blockIdx.y, b = blockIdx.z;
    const int tid = threadIdx.x;
    const long base = (long)(b * NT) * NC + h * HDIM;   // row s offset: base + s*NC

    if (tid < HDIM) qs[tid] = Q[base + (long)t * NC + tid];
    __syncthreads();

    const int nS = t + 1;

    // scores
    for (int s0 = 0; s0 < nS; s0 += 128) {
        int ns = min(128, nS - s0);
        for (int i = tid; i < ns * (HDIM/4); i += 128) {
            int r = i >> 4, d = (i & 15) * 4;
            float4 v = *reinterpret_cast<const float4*>(&K[base + (long)(s0 + r) * NC + d]);
            ks[r][d+0] = v.x; ks[r][d+1] = v.y; ks[r][d+2] = v.z; ks[r][d+3] = v.w;
        }
        __syncthreads();
        for (int s = tid; s < ns; s += 128) {
            float dot = 0.f;
            #pragma unroll
            for (int d = 0; d < HDIM; d++) dot += qs[d] * ks[s][d];
            sc[s0 + s] = dot * 0.125f;   // HD^-0.5
        }
        __syncthreads();
    }

    // softmax over sc[0..nS)
    float m = -INFINITY;
    for (int s = tid; s < nS; s += 128) m = fmaxf(m, sc[s]);
    red[tid] = m; __syncthreads();
    for (int st = 64; st > 0; st >>= 1) {
        if (tid < st) red[tid] = fmaxf(red[tid], red[tid + st]);
        __syncthreads();
    }
    m = red[0]; __syncthreads();
    float sum = 0.f;
    for (int s = tid; s < nS; s += 128) {
        float e = __expf(sc[s] - m);
        sc[s] = e;
        sum += e;
    }
    red[tid] = sum; __syncthreads();
    for (int st = 64; st > 0; st >>= 1) {
        if (tid < st) red[tid] += red[tid + st];
        __syncthreads();
    }
    float inv = 1.0f / red[0];
    __syncthreads();

    // y = p @ V
    float acc = 0.f;
    const int d = tid & 63;
    const int half = tid >> 6;
    for (int s0 = 0; s0 < nS; s0 += 128) {
        int ns = min(128, nS - s0);
        for (int i = tid; i < ns * (HDIM/4); i += 128) {
            int r = i >> 4, dd = (i & 15) * 4;
            float4 v = *reinterpret_cast<const float4*>(&Vv[base + (long)(s0 + r) * NC + dd]);
            ks[r][dd+0] = v.x; ks[r][dd+1] = v.y; ks[r][dd+2] = v.z; ks[r][dd+3] = v.w;
        }
        __syncthreads();
        for (int s = half; s < ns; s += 2) acc += sc[s0 + s] * ks[s][d];
        __syncthreads();
    }
    part[half][d] = acc;
    __syncthreads();
    if (tid < HDIM)
        Y[(long)(b * NT + t) * NC + h * HDIM + tid] = (part[0][tid] + part[1][tid]) * inv;
}

// ---------------- host driver ----------------
static void run_gemm(int M, int N, int K, const float* A, const float* Bm,
                     const float* bias, const float* res, float* Cm,
                     bool useBias, bool useRelu, bool useRes) {
    dim3 grid(N / 128, M / 128);
    if (useBias && useRelu && !useRes)
        sgemm_kernel<true, true, false><<<grid, 256>>>(M, N, K, A, Bm, bias, res, Cm);
    else if (useBias && !useRelu && useRes)
        sgemm_kernel<true, false, true><<<grid, 256>>>(M, N, K, A, Bm, bias, res, Cm);
    else
        sgemm_kernel<false, false, false><<<grid, 256>>>(M, N, K, A, Bm, bias, res, Cm);
}

extern "C" void kernel_launch(void* const* d_in, const int* in_sizes, int n_in,
                              void* d_out, int out_size) {
    const int*   idx   = (const int*)  d_in[0];
    const float* tok   = (const float*)d_in[1];
    const float* pos   = (const float*)d_in[2];
    const float* wq    = (const float*)d_in[3];
    const float* wk    = (const float*)d_in[4];
    const float* wv    = (const float*)d_in[5];
    const float* wo    = (const float*)d_in[6];
    const float* bo    = (const float*)d_in[7];
    const float* ln1g  = (const float*)d_in[8];
    const float* ln1b  = (const float*)d_in[9];
    const float* ln2g  = (const float*)d_in[10];
    const float* ln2b  = (const float*)d_in[11];
    const float* w1    = (const float*)d_in[12];
    const float* b1    = (const float*)d_in[13];
    const float* w2    = (const float*)d_in[14];
    const float* b2    = (const float*)d_in[15];
    const float* lnfg  = (const float*)d_in[16];
    const float* lnfb  = (const float*)d_in[17];
    const float* wlm   = (const float*)d_in[18];
    float* out = (float*)d_out;

    float *x, *xn, *q, *k, *v, *y, *hbuf;
    cudaGetSymbolAddress((void**)&x,    g_x);
    cudaGetSymbolAddress((void**)&xn,   g_xn);
    cudaGetSymbolAddress((void**)&q,    g_q);
    cudaGetSymbolAddress((void**)&k,    g_k);
    cudaGetSymbolAddress((void**)&v,    g_v);
    cudaGetSymbolAddress((void**)&y,    g_y);
    cudaGetSymbolAddress((void**)&hbuf, g_h);

    embed_kernel<<<MROWS, 256>>>(idx, tok, pos);

    for (int l = 0; l < NL; l++) {
        const long wOff = (long)l * NC * NC;
        ln_kernel<<<MROWS, 256>>>(x, ln1g + l * NC, ln1b + l * NC, xn);
        run_gemm(MROWS, NC, NC, xn, wq + wOff, nullptr, nullptr, q, false, false, false);
        run_gemm(MROWS, NC, NC, xn, wk + wOff, nullptr, nullptr, k, false, false, false);
        run_gemm(MROWS, NC, NC, xn, wv + wOff, nullptr, nullptr, v, false, false, false);
        attn_kernel<<<dim3(NT, NH, NB), 128>>>(q, k, v, y);
        run_gemm(MROWS, NC, NC, y, wo + wOff, bo + l * NC, x, x, true, false, true);
        ln_kernel<<<MROWS, 256>>>(x, ln2g + l * NC, ln2b + l * NC, xn);
        run_gemm(MROWS, NF, NC, xn, w1 + (long)l * NC * NF, b1 + (long)l * NF,
                 nullptr, hbuf, true, true, false);
        run_gemm(MROWS, NC, NF, hbuf, w2 + (long)l * NF * NC, b2 + l * NC,
                 x, x, true, false, true);
    }

    ln_kernel<<<MROWS, 256>>>(x, lnfg, lnfb, xn);
    run_gemm(MROWS, NV, NC, xn, wlm, nullptr, nullptr, out, false, false, false);
}

// round 5
// speedup vs baseline: 2.2106x; 2.2106x over previous
#include <cuda_runtime.h>
#include <cuda_bf16.h>
#include <math.h>
#include <stdint.h>

#define NL 12
#define NH 16
#define NC 1024
#define NT 512
#define NB 4
#define HDIM 64
#define NF 4096
#define NV 32000
#define MROWS (NB*NT)   // 2048
#define C3 (3*NC)       // 3072
#define LN_EPS 1e-5f

typedef __nv_bfloat16 bf16;
typedef __nv_bfloat162 bf162;

// ---------------- static scratch ----------------
__device__ float g_x   [MROWS*NC];
__device__ float g_qkv [MROWS*C3];
__device__ bf16  g_xn_h[MROWS*NC];
__device__ bf16  g_xn_l[MROWS*NC];
__device__ bf16  g_y_h [MROWS*NC];
__device__ bf16  g_y_l [MROWS*NC];
__device__ bf16  g_h_h [MROWS*NF];
__device__ bf16  g_h_l [MROWS*NF];

// split weights
__device__ bf16 g_wqkv_h[(long)NL*NC*C3];
__device__ bf16 g_wqkv_l[(long)NL*NC*C3];
__device__ bf16 g_wo_h  [(long)NL*NC*NC];
__device__ bf16 g_wo_l  [(long)NL*NC*NC];
__device__ bf16 g_w1_h  [(long)NL*NC*NF];
__device__ bf16 g_w1_l  [(long)NL*NC*NF];
__device__ bf16 g_w2_h  [(long)NL*NF*NC];
__device__ bf16 g_w2_l  [(long)NL*NF*NC];
__device__ bf16 g_lm_h  [(long)NC*NV];
__device__ bf16 g_lm_l  [(long)NC*NV];

__device__ __forceinline__ void split2(float v, bf16& h, bf16& l) {
    h = __float2bfloat16(v);
    l = __float2bfloat16(v - __bfloat162float(h));
}

// ---------------- conversion kernels ----------------
__global__ void split_kernel(const float* __restrict__ in,
                             bf16* __restrict__ oh, bf16* __restrict__ ol, long n) {
    for (long i = (long)blockIdx.x * blockDim.x + threadIdx.x; i < n;
         i += (long)gridDim.x * blockDim.x) {
        float v = in[i];
        bf16 h, l; split2(v, h, l);
        oh[i] = h; ol[i] = l;
    }
}

__global__ void pack_qkv_kernel(const float* __restrict__ wq,
                                const float* __restrict__ wk,
                                const float* __restrict__ wv,
                                bf16* __restrict__ oh, bf16* __restrict__ ol, long n) {
    for (long i = (long)blockIdx.x * blockDim.x + threadIdx.x; i < n;
         i += (long)gridDim.x * blockDim.x) {
        long lk = i / C3;        // l*NC + k
        int  j  = (int)(i % C3);
        int sel = j >> 10, jj = j & 1023;
        const float* src = (sel == 0) ? wq : (sel == 1) ? wk : wv;
        float v = src[lk * NC + jj];
        bf16 h, l; split2(v, h, l);
        oh[i] = h; ol[i] = l;
    }
}

// ---------------- embedding ----------------
__global__ void embed_kernel(const int* __restrict__ idx,
                             const float* __restrict__ tok,
                             const float* __restrict__ pos) {
    int row = blockIdx.x, t = row % NT;
    int tk = idx[row];
    const float4* tr = (const float4*)(tok + (long)tk * NC);
    const float4* pr = (const float4*)(pos + (long)t  * NC);
    float4* xr = (float4*)(g_x + (long)row * NC);
    for (int c = threadIdx.x; c < NC / 4; c += blockDim.x) {
        float4 a = tr[c], b = pr[c];
        a.x += b.x; a.y += b.y; a.z += b.z; a.w += b.w;
        xr[c] = a;
    }
}

// ---------------- layernorm + split (256 thr/row) ----------------
__global__ __launch_bounds__(256)
void ln_split_kernel(const float* __restrict__ x,
                     const float* __restrict__ gg,
                     const float* __restrict__ bb,
                     bf16* __restrict__ oh, bf16* __restrict__ ol) {
    __shared__ float rs[8], rs2[8];
    const int row = blockIdx.x, tid = threadIdx.x;
    const float4* xr = (const float4*)(x + (long)row * NC);
    float4 v = xr[tid];
    float s  = v.x + v.y + v.z + v.w;
    float s2 = v.x*v.x + v.y*v.y + v.z*v.z + v.w*v.w;
    #pragma unroll
    for (int off = 16; off > 0; off >>= 1) {
        s  += __shfl_xor_sync(0xffffffff, s,  off);
        s2 += __shfl_xor_sync(0xffffffff, s2, off);
    }
    if ((tid & 31) == 0) { rs[tid >> 5] = s; rs2[tid >> 5] = s2; }
    __syncthreads();
    if (tid < 8) {
        s = rs[tid]; s2 = rs2[tid];
        #pragma unroll
        for (int off = 4; off > 0; off >>= 1) {
            s  += __shfl_xor_sync(0xff, s,  off);
            s2 += __shfl_xor_sync(0xff, s2, off);
        }
        if (tid == 0) { rs[0] = s; rs2[0] = s2; }
    }
    __syncthreads();
    float mean = rs[0] * (1.0f / NC);
    float var  = rs2[0] * (1.0f / NC) - mean * mean;
    float rstd = rsqrtf(var + LN_EPS);
    const float4* g4 = (const float4*)gg;
    const float4* b4 = (const float4*)bb;
    float4 g = g4[tid], bv = b4[tid];
    float o0 = (v.x - mean) * rstd * g.x + bv.x;
    float o1 = (v.y - mean) * rstd * g.y + bv.y;
    float o2 = (v.z - mean) * rstd * g.z + bv.z;
    float o3 = (v.w - mean) * rstd * g.w + bv.w;
    bf16 h0,l0,h1,l1,h2,l2,h3,l3;
    split2(o0,h0,l0); split2(o1,h1,l1); split2(o2,h2,l2); split2(o3,h3,l3);
    bf162* oh2 = (bf162*)(oh + (long)row * NC);
    bf162* ol2 = (bf162*)(ol + (long)row * NC);
    oh2[tid*2]   = bf162(h0, h1);
    oh2[tid*2+1] = bf162(h2, h3);
    ol2[tid*2]   = bf162(l0, l1);
    ol2[tid*2+1] = bf162(l2, l3);
}

// ---------------- mma.sync helpers ----------------
__device__ __forceinline__ void ldsm_x4(uint32_t addr, uint32_t& r0, uint32_t& r1,
                                        uint32_t& r2, uint32_t& r3) {
    asm volatile("ldmatrix.sync.aligned.m8n8.x4.shared.b16 {%0,%1,%2,%3},[%4];"
                 : "=r"(r0), "=r"(r1), "=r"(r2), "=r"(r3) : "r"(addr));
}
__device__ __forceinline__ void ldsm_x4_t(uint32_t addr, uint32_t& r0, uint32_t& r1,
                                          uint32_t& r2, uint32_t& r3) {
    asm volatile("ldmatrix.sync.aligned.m8n8.x4.trans.shared.b16 {%0,%1,%2,%3},[%4];"
                 : "=r"(r0), "=r"(r1), "=r"(r2), "=r"(r3) : "r"(addr));
}
__device__ __forceinline__ void mma_bf16(float* c, const uint32_t* a, const uint32_t* b) {
    asm volatile(
        "mma.sync.aligned.m16n8k16.row.col.f32.bf16.bf16.f32 "
        "{%0,%1,%2,%3},{%4,%5,%6,%7},{%8,%9},{%0,%1,%2,%3};"
        : "+f"(c[0]), "+f"(c[1]), "+f"(c[2]), "+f"(c[3])
        : "r"(a[0]), "r"(a[1]), "r"(a[2]), "r"(a[3]), "r"(b[0]), "r"(b[1]));
}
__device__ __forceinline__ void cpa16(uint32_t s, const void* g) {
    asm volatile("cp.async.cg.shared.global [%0],[%1],16;" :: "r"(s), "l"(g));
}

// ---------------- split-bf16 tensor-core GEMM ----------------
// C(MxN) = Ah@Bh + Al@Bh + Ah@Bl, fp32 accum.
// BM=128 BN=128 BK=64, 256 threads (8 warps as 4x2), warp tile 32x64.
// smem/stage: Ah 16K | Al 16K | Bh 16K | Bl 16K = 64K; 2 stages = 128K dynamic.
// EPI: 0 = fp32 out; 1 = +bias +res, fp32 out; 2 = +bias, relu, split bf16 out.
template<int EPI>
__global__ __launch_bounds__(256)
void mma_gemm(int M, int N, int K,
              const bf16* __restrict__ Ah, const bf16* __restrict__ Al,
              const bf16* __restrict__ Bh, const bf16* __restrict__ Bl,
              const float* __restrict__ bias, const float* __restrict__ res,
              float* __restrict__ Cf, bf16* __restrict__ Ch, bf16* __restrict__ Cl) {
    extern __shared__ char smem[];
    const uint32_t sbase0 = (uint32_t)__cvta_generic_to_shared(smem);
    const int tid  = threadIdx.x;
    const int lane = tid & 31, warp = tid >> 5;
    const int wm = warp >> 1, wn = warp & 1;        // 4 x 2 warps
    const int m0 = blockIdx.y * 128, n0 = blockIdx.x * 128;
    const int r8 = lane & 7, grp = lane >> 3;
    const int g = lane >> 2, t4 = lane & 3;

    float acc[2][8][4];
    #pragma unroll
    for (int i = 0; i < 2; i++)
        #pragma unroll
        for (int j = 0; j < 8; j++)
            #pragma unroll
            for (int r = 0; r < 4; r++) acc[i][j][r] = 0.f;

    const int T = K >> 6;

    // ---- stage loader ----
    auto load_stage = [&](int stage, int k0) {
        uint32_t sb = sbase0 + stage * 65536;
        #pragma unroll 2
        for (int c = tid; c < 1024; c += 256) {
            int m = c >> 3, kc = c & 7;
            uint32_t soff = m * 128 + (((kc ^ (m & 7))) << 4);
            size_t goff = (size_t)(m0 + m) * K + k0 + (kc << 3);
            cpa16(sb + soff,         Ah + goff);
            cpa16(sb + 16384 + soff, Al + goff);
        }
        #pragma unroll 2
        for (int c = tid; c < 1024; c += 256) {
            int k = c >> 4, nc = c & 15;
            uint32_t soff = k * 256 + (((nc ^ (k & 7))) << 4);
            size_t goff = (size_t)(k0 + k) * N + n0 + (nc << 3);
            cpa16(sb + 32768 + soff, Bh + goff);
            cpa16(sb + 49152 + soff, Bl + goff);
        }
    };

    load_stage(0, 0);
    asm volatile("cp.async.commit_group;");

    for (int t = 0; t < T; t++) {
        if (t + 1 < T) {
            load_stage((t + 1) & 1, (t + 1) << 6);
            asm volatile("cp.async.commit_group;");
            asm volatile("cp.async.wait_group 1;");
        } else {
            asm volatile("cp.async.wait_group 0;");
        }
        __syncthreads();

        uint32_t sA  = sbase0 + (t & 1) * 65536;
        uint32_t sAl = sA + 16384;
        uint32_t sB  = sA + 32768;
        uint32_t sBl = sA + 49152;

        #pragma unroll
        for (int kt = 0; kt < 4; kt++) {
            uint32_t ah[2][4], al_[2][4];
            #pragma unroll
            for (int i = 0; i < 2; i++) {
                int row = wm * 32 + i * 16 + r8 + ((grp & 1) << 3);
                int kch = kt * 2 + (grp >> 1);
                uint32_t off = row * 128 + (((kch ^ (row & 7))) << 4);
                ldsm_x4(sA  + off, ah[i][0],  ah[i][1],  ah[i][2],  ah[i][3]);
                ldsm_x4(sAl + off, al_[i][0], al_[i][1], al_[i][2], al_[i][3]);
            }
            uint32_t bh[8][2], bl_[8][2];
            #pragma unroll
            for (int j4 = 0; j4 < 4; j4++) {
                int k = kt * 16 + r8 + ((grp & 1) << 3);
                int nch = wn * 8 + j4 * 2 + (grp >> 1);
                uint32_t off = k * 256 + (((nch ^ (k & 7))) << 4);
                ldsm_x4_t(sB  + off, bh[2*j4][0], bh[2*j4][1], bh[2*j4+1][0], bh[2*j4+1][1]);
                ldsm_x4_t(sBl + off, bl_[2*j4][0], bl_[2*j4][1], bl_[2*j4+1][0], bl_[2*j4+1][1]);
            }
            #pragma unroll
            for (int i = 0; i < 2; i++)
                #pragma unroll
                for (int j = 0; j < 8; j++) {
                    mma_bf16(acc[i][j], ah[i],  bh[j]);
                    mma_bf16(acc[i][j], al_[i], bh[j]);
                    mma_bf16(acc[i][j], ah[i],  bl_[j]);
                }
        }
        __syncthreads();
    }

    // ---- epilogue ----
    #pragma unroll
    for (int i = 0; i < 2; i++) {
        int ra = m0 + wm * 32 + i * 16 + g;
        int rb = ra + 8;
        #pragma unroll
        for (int j = 0; j < 8; j++) {
            int c = n0 + wn * 64 + j * 8 + t4 * 2;
            float v0 = acc[i][j][0], v1 = acc[i][j][1];
            float v2 = acc[i][j][2], v3 = acc[i][j][3];
            if (EPI >= 1) {
                float b0 = bias[c], b1 = bias[c + 1];
                v0 += b0; v1 += b1; v2 += b0; v3 += b1;
            }
            if (EPI == 1) {
                const float2 ra2 = *(const float2*)(res + (size_t)ra * N + c);
                const float2 rb2 = *(const float2*)(res + (size_t)rb * N + c);
                v0 += ra2.x; v1 += ra2.y; v2 += rb2.x; v3 += rb2.y;
            }
            if (EPI <= 1) {
                *(float2*)(Cf + (size_t)ra * N + c) = make_float2(v0, v1);
                *(float2*)(Cf + (size_t)rb * N + c) = make_float2(v2, v3);
            } else {
                v0 = fmaxf(v0, 0.f); v1 = fmaxf(v1, 0.f);
                v2 = fmaxf(v2, 0.f); v3 = fmaxf(v3, 0.f);
                bf16 h0,l0,h1,l1,h2,l2,h3,l3;
                split2(v0,h0,l0); split2(v1,h1,l1);
                split2(v2,h2,l2); split2(v3,h3,l3);
                *(bf162*)(Ch + (size_t)ra * N + c) = bf162(h0, h1);
                *(bf162*)(Ch + (size_t)rb * N + c) = bf162(h2, h3);
                *(bf162*)(Cl + (size_t)ra * N + c) = bf162(l0, l1);
                *(bf162*)(Cl + (size_t)rb * N + c) = bf162(l2, l3);
            }
        }
    }
}

// ---------------- causal attention (reads packed qkv fp32, writes split y) ----------------
__global__ __launch_bounds__(128)
void attn_kernel(const float* __restrict__ QKV,
                 bf16* __restrict__ Yh, bf16* __restrict__ Yl) {
    __shared__ float qs[HDIM];
    __shared__ float ks[128][HDIM + 1];
    __shared__ float sc[NT];
    __shared__ float red[128];
    __shared__ float part[2][HDIM];

    const int t = blockIdx.x, h = blockIdx.y, b = blockIdx.z;
    const int tid = threadIdx.x;
    const long baseQ = (long)(b * NT) * C3 + h * HDIM;
    const long baseK = baseQ + NC;
    const long baseV = baseQ + 2 * NC;

    if (tid < HDIM) qs[tid] = QKV[baseQ + (long)t * C3 + tid];
    __syncthreads();

    const int nS = t + 1;

    for (int s0 = 0; s0 < nS; s0 += 128) {
        int ns = min(128, nS - s0);
        for (int i = tid; i < ns * (HDIM/4); i += 128) {
            int r = i >> 4, d = (i & 15) * 4;
            float4 v = *reinterpret_cast<const float4*>(&QKV[baseK + (long)(s0 + r) * C3 + d]);
            ks[r][d+0] = v.x; ks[r][d+1] = v.y; ks[r][d+2] = v.z; ks[r][d+3] = v.w;
        }
        __syncthreads();
        for (int s = tid; s < ns; s += 128) {
            float dot = 0.f;
            #pragma unroll
            for (int d = 0; d < HDIM; d++) dot += qs[d] * ks[s][d];
            sc[s0 + s] = dot * 0.125f;
        }
        __syncthreads();
    }

    float m = -INFINITY;
    for (int s = tid; s < nS; s += 128) m = fmaxf(m, sc[s]);
    red[tid] = m; __syncthreads();
    for (int st = 64; st > 0; st >>= 1) {
        if (tid < st) red[tid] = fmaxf(red[tid], red[tid + st]);
        __syncthreads();
    }
    m = red[0]; __syncthreads();
    float sum = 0.f;
    for (int s = tid; s < nS; s += 128) {
        float e = __expf(sc[s] - m);
        sc[s] = e; sum += e;
    }
    red[tid] = sum; __syncthreads();
    for (int st = 64; st > 0; st >>= 1) {
        if (tid < st) red[tid] += red[tid + st];
        __syncthreads();
    }
    float inv = 1.0f / red[0];
    __syncthreads();

    float acc = 0.f;
    const int d = tid & 63, half = tid >> 6;
    for (int s0 = 0; s0 < nS; s0 += 128) {
        int ns = min(128, nS - s0);
        for (int i = tid; i < ns * (HDIM/4); i += 128) {
            int r = i >> 4, dd = (i & 15) * 4;
            float4 v = *reinterpret_cast<const float4*>(&QKV[baseV + (long)(s0 + r) * C3 + dd]);
            ks[r][dd+0] = v.x; ks[r][dd+1] = v.y; ks[r][dd+2] = v.z; ks[r][dd+3] = v.w;
        }
        __syncthreads();
        for (int s = half; s < ns; s += 2) acc += sc[s0 + s] * ks[s][d];
        __syncthreads();
    }
    part[half][d] = acc;
    __syncthreads();
    if (tid < HDIM) {
        float val = (part[0][tid] + part[1][tid]) * inv;
        bf16 hh, ll; split2(val, hh, ll);
        long o = (long)(b * NT + t) * NC + h * HDIM + tid;
        Yh[o] = hh; Yl[o] = ll;
    }
}

// ---------------- host driver ----------------
#define SMEM_GEMM 131072

extern "C" void kernel_launch(void* const* d_in, const int* in_sizes, int n_in,
                              void* d_out, int out_size) {
    const int*   idx  = (const int*)  d_in[0];
    const float* tok  = (const float*)d_in[1];
    const float* pos  = (const float*)d_in[2];
    const float* wq   = (const float*)d_in[3];
    const float* wk   = (const float*)d_in[4];
    const float* wv   = (const float*)d_in[5];
    const float* wo   = (const float*)d_in[6];
    const float* bo   = (const float*)d_in[7];
    const float* ln1g = (const float*)d_in[8];
    const float* ln1b = (const float*)d_in[9];
    const float* ln2g = (const float*)d_in[10];
    const float* ln2b = (const float*)d_in[11];
    const float* w1   = (const float*)d_in[12];
    const float* b1   = (const float*)d_in[13];
    const float* w2   = (const float*)d_in[14];
    const float* b2   = (const float*)d_in[15];
    const float* lnfg = (const float*)d_in[16];
    const float* lnfb = (const float*)d_in[17];
    const float* wlm  = (const float*)d_in[18];
    float* out = (float*)d_out;

    static bool attr_done = false;
    if (!attr_done) {
        cudaFuncSetAttribute(mma_gemm<0>, cudaFuncAttributeMaxDynamicSharedMemorySize, SMEM_GEMM);
        cudaFuncSetAttribute(mma_gemm<1>, cudaFuncAttributeMaxDynamicSharedMemorySize, SMEM_GEMM);
        cudaFuncSetAttribute(mma_gemm<2>, cudaFuncAttributeMaxDynamicSharedMemorySize, SMEM_GEMM);
        attr_done = true;
    }

    float *x, *qkv;
    bf16 *xnh, *xnl, *yh, *yl, *hh, *hl;
    bf16 *wqkvh, *wqkvl, *woh, *wol, *w1h, *w1l, *w2h, *w2l, *lmh, *lml;
    cudaGetSymbolAddress((void**)&x,     g_x);
    cudaGetSymbolAddress((void**)&qkv,   g_qkv);
    cudaGetSymbolAddress((void**)&xnh,   g_xn_h);
    cudaGetSymbolAddress((void**)&xnl,   g_xn_l);
    cudaGetSymbolAddress((void**)&yh,    g_y_h);
    cudaGetSymbolAddress((void**)&yl,    g_y_l);
    cudaGetSymbolAddress((void**)&hh,    g_h_h);
    cudaGetSymbolAddress((void**)&hl,    g_h_l);
    cudaGetSymbolAddress((void**)&wqkvh, g_wqkv_h);
    cudaGetSymbolAddress((void**)&wqkvl, g_wqkv_l);
    cudaGetSymbolAddress((void**)&woh,   g_wo_h);
    cudaGetSymbolAddress((void**)&wol,   g_wo_l);
    cudaGetSymbolAddress((void**)&w1h,   g_w1_h);
    cudaGetSymbolAddress((void**)&w1l,   g_w1_l);
    cudaGetSymbolAddress((void**)&w2h,   g_w2_h);
    cudaGetSymbolAddress((void**)&w2l,   g_w2_l);
    cudaGetSymbolAddress((void**)&lmh,   g_lm_h);
    cudaGetSymbolAddress((void**)&lml,   g_lm_l);

    // weight conversion
    pack_qkv_kernel<<<4096, 256>>>(wq, wk, wv, wqkvh, wqkvl, (long)NL*NC*C3);
    split_kernel<<<4096, 256>>>(wo,  woh, wol, (long)NL*NC*NC);
    split_kernel<<<8192, 256>>>(w1,  w1h, w1l, (long)NL*NC*NF);
    split_kernel<<<8192, 256>>>(w2,  w2h, w2l, (long)NL*NF*NC);
    split_kernel<<<8192, 256>>>(wlm, lmh, lml, (long)NC*NV);

    embed_kernel<<<MROWS, 256>>>(idx, tok, pos);

    for (int l = 0; l < NL; l++) {
        const long oQ = (long)l * NC * C3;
        const long oO = (long)l * NC * NC;
        const long o1 = (long)l * NC * NF;
        const long o2 = (long)l * NF * NC;

        ln_split_kernel<<<MROWS, 256>>>(x, ln1g + l*NC, ln1b + l*NC, xnh, xnl);
        mma_gemm<0><<<dim3(C3/128, MROWS/128), 256, SMEM_GEMM>>>(
            MROWS, C3, NC, xnh, xnl, wqkvh + oQ, wqkvl + oQ,
            nullptr, nullptr, qkv, nullptr, nullptr);
        attn_kernel<<<dim3(NT, NH, NB), 128>>>(qkv, yh, yl);
        mma_gemm<1><<<dim3(NC/128, MROWS/128), 256, SMEM_GEMM>>>(
            MROWS, NC, NC, yh, yl, woh + oO, wol + oO,
            bo + l*NC, x, x, nullptr, nullptr);
        ln_split_kernel<<<MROWS, 256>>>(x, ln2g + l*NC, ln2b + l*NC, xnh, xnl);
        mma_gemm<2><<<dim3(NF/128, MROWS/128), 256, SMEM_GEMM>>>(
            MROWS, NF, NC, xnh, xnl, w1h + o1, w1l + o1,
            b1 + l*NF, nullptr, nullptr, hh, hl);
        mma_gemm<1><<<dim3(NC/128, MROWS/128), 256, SMEM_GEMM>>>(
            MROWS, NC, NF, hh, hl, w2h + o2, w2l + o2,
            b2 + l*NC, x, x, nullptr, nullptr);
    }

    ln_split_kernel<<<MROWS, 256>>>(x, lnfg, lnfb, xnh, xnl);
    mma_gemm<0><<<dim3(NV/128, MROWS/128), 256, SMEM_GEMM>>>(
        MROWS, NV, NC, xnh, xnl, lmh, lml,
        nullptr, nullptr, out, nullptr, nullptr);
}

// round 7
// speedup vs baseline: 2.2794x; 1.0311x over previous
#include <cuda_runtime.h>
#include <cuda_bf16.h>
#include <math.h>
#include <stdint.h>

#define NL 12
#define NH 16
#define NC 1024
#define NT 512
#define NB 4
#define HDIM 64
#define NF 4096
#define NV 32000
#define MROWS (NB*NT)   // 2048
#define C3 (3*NC)       // 3072
#define LN_EPS 1e-5f

typedef __nv_bfloat16 bf16;
typedef __nv_bfloat162 bf162;

// ---------------- static scratch ----------------
__device__ float g_x   [MROWS*NC];
__device__ float g_qkv [MROWS*C3];
__device__ bf16  g_xn_h[MROWS*NC];
__device__ bf16  g_xn_l[MROWS*NC];
__device__ bf16  g_y_h [MROWS*NC];
__device__ bf16  g_y_l [MROWS*NC];
__device__ bf16  g_h_h [MROWS*NF];
__device__ bf16  g_h_l [MROWS*NF];

// split weights, K-major W[K,N] (as in reference)
__device__ bf16 g_wqkv_h[(long)NL*NC*C3];
__device__ bf16 g_wqkv_l[(long)NL*NC*C3];
__device__ bf16 g_wo_h  [(long)NL*NC*NC];
__device__ bf16 g_wo_l  [(long)NL*NC*NC];
__device__ bf16 g_w1_h  [(long)NL*NC*NF];
__device__ bf16 g_w1_l  [(long)NL*NC*NF];
__device__ bf16 g_w2_h  [(long)NL*NF*NC];
__device__ bf16 g_w2_l  [(long)NL*NF*NC];
__device__ bf16 g_lm_h  [(long)NC*NV];
__device__ bf16 g_lm_l  [(long)NC*NV];

__device__ __forceinline__ void split2(float v, bf16& h, bf16& l) {
    h = __float2bfloat16(v);
    l = __float2bfloat16(v - __bfloat162float(h));
}

// ---------------- conversion kernels ----------------
__global__ void split_kernel(const float* __restrict__ in,
                             bf16* __restrict__ oh, bf16* __restrict__ ol, long n) {
    for (long i = (long)blockIdx.x * blockDim.x + threadIdx.x; i < n;
         i += (long)gridDim.x * blockDim.x) {
        float v = in[i];
        bf16 h, l; split2(v, h, l);
        oh[i] = h; ol[i] = l;
    }
}

__global__ void pack_qkv_kernel(const float* __restrict__ wq,
                                const float* __restrict__ wk,
                                const float* __restrict__ wv,
                                bf16* __restrict__ oh, bf16* __restrict__ ol, long n) {
    for (long i = (long)blockIdx.x * blockDim.x + threadIdx.x; i < n;
         i += (long)gridDim.x * blockDim.x) {
        long lk = i / C3;        // l*NC + k
        int  j  = (int)(i % C3);
        int sel = j >> 10, jj = j & 1023;
        const float* src = (sel == 0) ? wq : (sel == 1) ? wk : wv;
        float v = src[lk * NC + jj];
        bf16 h, l; split2(v, h, l);
        oh[i] = h; ol[i] = l;
    }
}

// ---------------- embedding ----------------
__global__ void embed_kernel(const int* __restrict__ idx,
                             const float* __restrict__ tok,
                             const float* __restrict__ pos) {
    int row = blockIdx.x, t = row % NT;
    int tk = idx[row];
    const float4* tr = (const float4*)(tok + (long)tk * NC);
    const float4* pr = (const float4*)(pos + (long)t  * NC);
    float4* xr = (float4*)(g_x + (long)row * NC);
    for (int c = threadIdx.x; c < NC / 4; c += blockDim.x) {
        float4 a = tr[c], b = pr[c];
        a.x += b.x; a.y += b.y; a.z += b.z; a.w += b.w;
        xr[c] = a;
    }
}

// ---------------- layernorm + split (256 thr/row) ----------------
__global__ __launch_bounds__(256)
void ln_split_kernel(const float* __restrict__ x,
                     const float* __restrict__ gg,
                     const float* __restrict__ bb,
                     bf16* __restrict__ oh, bf16* __restrict__ ol) {
    __shared__ float rs[8], rs2[8];
    const int row = blockIdx.x, tid = threadIdx.x;
    const float4* xr = (const float4*)(x + (long)row * NC);
    float4 v = xr[tid];
    float s  = v.x + v.y + v.z + v.w;
    float s2 = v.x*v.x + v.y*v.y + v.z*v.z + v.w*v.w;
    #pragma unroll
    for (int off = 16; off > 0; off >>= 1) {
        s  += __shfl_xor_sync(0xffffffff, s,  off);
        s2 += __shfl_xor_sync(0xffffffff, s2, off);
    }
    if ((tid & 31) == 0) { rs[tid >> 5] = s; rs2[tid >> 5] = s2; }
    __syncthreads();
    if (tid < 8) {
        s = rs[tid]; s2 = rs2[tid];
        #pragma unroll
        for (int off = 4; off > 0; off >>= 1) {
            s  += __shfl_xor_sync(0xff, s,  off);
            s2 += __shfl_xor_sync(0xff, s2, off);
        }
        if (tid == 0) { rs[0] = s; rs2[0] = s2; }
    }
    __syncthreads();
    float mean = rs[0] * (1.0f / NC);
    float var  = rs2[0] * (1.0f / NC) - mean * mean;
    float rstd = rsqrtf(var + LN_EPS);
    const float4* g4 = (const float4*)gg;
    const float4* b4 = (const float4*)bb;
    float4 g = g4[tid], bv = b4[tid];
    float o0 = (v.x - mean) * rstd * g.x + bv.x;
    float o1 = (v.y - mean) * rstd * g.y + bv.y;
    float o2 = (v.z - mean) * rstd * g.z + bv.z;
    float o3 = (v.w - mean) * rstd * g.w + bv.w;
    bf16 h0,l0,h1,l1,h2,l2,h3,l3;
    split2(o0,h0,l0); split2(o1,h1,l1); split2(o2,h2,l2); split2(o3,h3,l3);
    bf162* oh2 = (bf162*)(oh + (long)row * NC);
    bf162* ol2 = (bf162*)(ol + (long)row * NC);
    oh2[tid*2]   = bf162(h0, h1);
    oh2[tid*2+1] = bf162(h2, h3);
    ol2[tid*2]   = bf162(l0, l1);
    ol2[tid*2+1] = bf162(l2, l3);
}

// ---------------- mma.sync helpers ----------------
__device__ __forceinline__ void ldsm_x4(uint32_t addr, uint32_t& r0, uint32_t& r1,
                                        uint32_t& r2, uint32_t& r3) {
    asm volatile("ldmatrix.sync.aligned.m8n8.x4.shared.b16 {%0,%1,%2,%3},[%4];"
                 : "=r"(r0), "=r"(r1), "=r"(r2), "=r"(r3) : "r"(addr));
}
__device__ __forceinline__ void ldsm_x4_t(uint32_t addr, uint32_t& r0, uint32_t& r1,
                                          uint32_t& r2, uint32_t& r3) {
    asm volatile("ldmatrix.sync.aligned.m8n8.x4.trans.shared.b16 {%0,%1,%2,%3},[%4];"
                 : "=r"(r0), "=r"(r1), "=r"(r2), "=r"(r3) : "r"(addr));
}
__device__ __forceinline__ void mma_bf16(float* c, const uint32_t* a, const uint32_t* b) {
    asm volatile(
        "mma.sync.aligned.m16n8k16.row.col.f32.bf16.bf16.f32 "
        "{%0,%1,%2,%3},{%4,%5,%6,%7},{%8,%9},{%0,%1,%2,%3};"
        : "+f"(c[0]), "+f"(c[1]), "+f"(c[2]), "+f"(c[3])
        : "r"(a[0]), "r"(a[1]), "r"(a[2]), "r"(a[3]), "r"(b[0]), "r"(b[1]));
}
__device__ __forceinline__ void cpa16(uint32_t s, const void* g) {
    asm volatile("cp.async.cg.shared.global [%0],[%1],16;" :: "r"(s), "l"(g));
}

// ---------------- split-bf16 tensor-core GEMM ----------------
// C(MxN) = Ah@Bh + Al@Bh + Ah@Bl, fp32 accum.
// BM=128 BN=128 BK=32, 256 threads (8 warps as 4x2), warp tile 32x64.
// smem/stage: Ah 8K | Al 8K | Bh 8K | Bl 8K = 32K; 2 stages = 64K -> 2 CTAs/SM.
// A stage: [128 rows][32 bf16] 64B rows, swizzle chunk c^((r>>1)&3).
// B stage: [32 rows(k)][128 bf16(n)] 256B rows, swizzle chunk nc^(k&7).
// EPI: 0 = fp32 out; 1 = +bias +res fp32 out; 2 = +bias relu split bf16 out.
#define SMEM_GEMM 65536

template<int EPI>
__global__ __launch_bounds__(256, 2)
void mma_gemm(int M, int N, int K,
              const bf16* __restrict__ Ah, const bf16* __restrict__ Al,
              const bf16* __restrict__ Bh, const bf16* __restrict__ Bl,
              const float* __restrict__ bias, const float* __restrict__ res,
              float* __restrict__ Cf, bf16* __restrict__ Ch, bf16* __restrict__ Cl) {
    extern __shared__ char smem[];
    const uint32_t sbase0 = (uint32_t)__cvta_generic_to_shared(smem);
    const int tid  = threadIdx.x;
    const int lane = tid & 31, warp = tid >> 5;
    const int wm = warp >> 1, wn = warp & 1;        // 4 x 2 warps
    const int m0 = blockIdx.y * 128, n0 = blockIdx.x * 128;
    const int r8 = lane & 7, grp = lane >> 3;
    const int g = lane >> 2, t4 = lane & 3;

    float acc[2][8][4];
    #pragma unroll
    for (int i = 0; i < 2; i++)
        #pragma unroll
        for (int j = 0; j < 8; j++)
            #pragma unroll
            for (int r = 0; r < 4; r++) acc[i][j][r] = 0.f;

    const int T = K >> 5;

    // ---- stage loader: 32KB per stage, 8 cp.async per thread ----
    auto load_stage = [&](int stage, int k0) {
        uint32_t sb = sbase0 + stage * 32768;
        #pragma unroll
        for (int it = 0; it < 2; it++) {
            int c = it * 256 + tid;          // 0..511
            int r = c >> 2, cc = c & 3;      // 4 x 16B chunks per 64B row
            uint32_t so = r * 64 + ((cc ^ ((r >> 1) & 3)) << 4);
            size_t ga = (size_t)(m0 + r) * K + k0 + (cc << 3);
            cpa16(sb +        so, Ah + ga);
            cpa16(sb + 8192 + so, Al + ga);
        }
        #pragma unroll
        for (int it = 0; it < 2; it++) {
            int c = it * 256 + tid;          // 0..511
            int k = c >> 4, nc = c & 15;     // 16 x 16B chunks per 256B row
            uint32_t so = k * 256 + ((nc ^ (k & 7)) << 4);
            size_t ga = (size_t)(k0 + k) * N + n0 + (nc << 3);
            cpa16(sb + 16384 + so, Bh + ga);
            cpa16(sb + 24576 + so, Bl + ga);
        }
    };

    load_stage(0, 0);
    asm volatile("cp.async.commit_group;");

    for (int t = 0; t < T; t++) {
        if (t + 1 < T) {
            load_stage((t + 1) & 1, (t + 1) << 5);
            asm volatile("cp.async.commit_group;");
            asm volatile("cp.async.wait_group 1;");
        } else {
            asm volatile("cp.async.wait_group 0;");
        }
        __syncthreads();

        uint32_t sA  = sbase0 + (t & 1) * 32768;
        uint32_t sAl = sA + 8192;
        uint32_t sB  = sA + 16384;
        uint32_t sBl = sA + 24576;

        #pragma unroll
        for (int kt = 0; kt < 2; kt++) {
            uint32_t ah[2][4], al_[2][4];
            #pragma unroll
            for (int i = 0; i < 2; i++) {
                int row = wm * 32 + i * 16 + r8 + ((grp & 1) << 3);
                int kc  = kt * 2 + (grp >> 1);
                uint32_t off = row * 64 + ((kc ^ ((row >> 1) & 3)) << 4);
                ldsm_x4(sA  + off, ah[i][0],  ah[i][1],  ah[i][2],  ah[i][3]);
                ldsm_x4(sAl + off, al_[i][0], al_[i][1], al_[i][2], al_[i][3]);
            }
            #pragma unroll
            for (int half = 0; half < 2; half++) {
                uint32_t bh[4][2], bl_[4][2];
                #pragma unroll
                for (int j4 = 0; j4 < 2; j4++) {
                    int k = kt * 16 + r8 + ((grp & 1) << 3);
                    int nch = wn * 8 + (half * 2 + j4) * 2 + (grp >> 1);
                    uint32_t off = k * 256 + ((nch ^ (k & 7)) << 4);
                    ldsm_x4_t(sB  + off, bh[2*j4][0],  bh[2*j4][1],  bh[2*j4+1][0],  bh[2*j4+1][1]);
                    ldsm_x4_t(sBl + off, bl_[2*j4][0], bl_[2*j4][1], bl_[2*j4+1][0], bl_[2*j4+1][1]);
                }
                #pragma unroll
                for (int i = 0; i < 2; i++)
                    #pragma unroll
                    for (int jl = 0; jl < 4; jl++) {
                        float* a = acc[i][half * 4 + jl];
                        mma_bf16(a, ah[i],  bh[jl]);
                        mma_bf16(a, al_[i], bh[jl]);
                        mma_bf16(a, ah[i],  bl_[jl]);
                    }
            }
        }
        __syncthreads();
    }

    // ---- epilogue ----
    #pragma unroll
    for (int i = 0; i < 2; i++) {
        int ra = m0 + wm * 32 + i * 16 + g;
        int rb = ra + 8;
        #pragma unroll
        for (int j = 0; j < 8; j++) {
            int c = n0 + wn * 64 + j * 8 + t4 * 2;
            float v0 = acc[i][j][0], v1 = acc[i][j][1];
            float v2 = acc[i][j][2], v3 = acc[i][j][3];
            if (EPI >= 1) {
                float b0 = bias[c], b1 = bias[c + 1];
                v0 += b0; v1 += b1; v2 += b0; v3 += b1;
            }
            if (EPI == 1) {
                const float2 ra2 = *(const float2*)(res + (size_t)ra * N + c);
                const float2 rb2 = *(const float2*)(res + (size_t)rb * N + c);
                v0 += ra2.x; v1 += ra2.y; v2 += rb2.x; v3 += rb2.y;
            }
            if (EPI <= 1) {
                *(float2*)(Cf + (size_t)ra * N + c) = make_float2(v0, v1);
                *(float2*)(Cf + (size_t)rb * N + c) = make_float2(v2, v3);
            } else {
                v0 = fmaxf(v0, 0.f); v1 = fmaxf(v1, 0.f);
                v2 = fmaxf(v2, 0.f); v3 = fmaxf(v3, 0.f);
                bf16 h0,l0,h1,l1,h2,l2,h3,l3;
                split2(v0,h0,l0); split2(v1,h1,l1);
                split2(v2,h2,l2); split2(v3,h3,l3);
                *(bf162*)(Ch + (size_t)ra * N + c) = bf162(h0, h1);
                *(bf162*)(Ch + (size_t)rb * N + c) = bf162(h2, h3);
                *(bf162*)(Cl + (size_t)ra * N + c) = bf162(l0, l1);
                *(bf162*)(Cl + (size_t)rb * N + c) = bf162(l2, l3);
            }
        }
    }
}

// ---------------- causal attention (reads packed qkv fp32, writes split y) ----------------
__global__ __launch_bounds__(128)
void attn_kernel(const float* __restrict__ QKV,
                 bf16* __restrict__ Yh, bf16* __restrict__ Yl) {
    __shared__ float qs[HDIM];
    __shared__ float ks[128][HDIM + 1];
    __shared__ float sc[NT];
    __shared__ float red[128];
    __shared__ float part[2][HDIM];

    const int t = blockIdx.x, h = blockIdx.y, b = blockIdx.z;
    const int tid = threadIdx.x;
    const long baseQ = (long)(b * NT) * C3 + h * HDIM;
    const long baseK = baseQ + NC;
    const long baseV = baseQ + 2 * NC;

    if (tid < HDIM) qs[tid] = QKV[baseQ + (long)t * C3 + tid];
    __syncthreads();

    const int nS = t + 1;

    for (int s0 = 0; s0 < nS; s0 += 128) {
        int ns = min(128, nS - s0);
        for (int i = tid; i < ns * (HDIM/4); i += 128) {
            int r = i >> 4, d = (i & 15) * 4;
            float4 v = *reinterpret_cast<const float4*>(&QKV[baseK + (long)(s0 + r) * C3 + d]);
            ks[r][d+0] = v.x; ks[r][d+1] = v.y; ks[r][d+2] = v.z; ks[r][d+3] = v.w;
        }
        __syncthreads();
        for (int s = tid; s < ns; s += 128) {
            float dot = 0.f;
            #pragma unroll
            for (int d = 0; d < HDIM; d++) dot += qs[d] * ks[s][d];
            sc[s0 + s] = dot * 0.125f;
        }
        __syncthreads();
    }

    float m = -INFINITY;
    for (int s = tid; s < nS; s += 128) m = fmaxf(m, sc[s]);
    red[tid] = m; __syncthreads();
    for (int st = 64; st > 0; st >>= 1) {
        if (tid < st) red[tid] = fmaxf(red[tid], red[tid + st]);
        __syncthreads();
    }
    m = red[0]; __syncthreads();
    float sum = 0.f;
    for (int s = tid; s < nS; s += 128) {
        float e = __expf(sc[s] - m);
        sc[s] = e; sum += e;
    }
    red[tid] = sum; __syncthreads();
    for (int st = 64; st > 0; st >>= 1) {
        if (tid < st) red[tid] += red[tid + st];
        __syncthreads();
    }
    float inv = 1.0f / red[0];
    __syncthreads();

    float acc = 0.f;
    const int d = tid & 63, half = tid >> 6;
    for (int s0 = 0; s0 < nS; s0 += 128) {
        int ns = min(128, nS - s0);
        for (int i = tid; i < ns * (HDIM/4); i += 128) {
            int r = i >> 4, dd = (i & 15) * 4;
            float4 v = *reinterpret_cast<const float4*>(&QKV[baseV + (long)(s0 + r) * C3 + dd]);
            ks[r][dd+0] = v.x; ks[r][dd+1] = v.y; ks[r][dd+2] = v.z; ks[r][dd+3] = v.w;
        }
        __syncthreads();
        for (int s = half; s < ns; s += 2) acc += sc[s0 + s] * ks[s][d];
        __syncthreads();
    }
    part[half][d] = acc;
    __syncthreads();
    if (tid < HDIM) {
        float val = (part[0][tid] + part[1][tid]) * inv;
        bf16 hh, ll; split2(val, hh, ll);
        long o = (long)(b * NT + t) * NC + h * HDIM + tid;
        Yh[o] = hh; Yl[o] = ll;
    }
}

// ---------------- host driver ----------------
extern "C" void kernel_launch(void* const* d_in, const int* in_sizes, int n_in,
                              void* d_out, int out_size) {
    const int*   idx  = (const int*)  d_in[0];
    const float* tok  = (const float*)d_in[1];
    const float* pos  = (const float*)d_in[2];
    const float* wq   = (const float*)d_in[3];
    const float* wk   = (const float*)d_in[4];
    const float* wv   = (const float*)d_in[5];
    const float* wo   = (const float*)d_in[6];
    const float* bo   = (const float*)d_in[7];
    const float* ln1g = (const float*)d_in[8];
    const float* ln1b = (const float*)d_in[9];
    const float* ln2g = (const float*)d_in[10];
    const float* ln2b = (const float*)d_in[11];
    const float* w1   = (const float*)d_in[12];
    const float* b1   = (const float*)d_in[13];
    const float* w2   = (const float*)d_in[14];
    const float* b2   = (const float*)d_in[15];
    const float* lnfg = (const float*)d_in[16];
    const float* lnfb = (const float*)d_in[17];
    const float* wlm  = (const float*)d_in[18];
    float* out = (float*)d_out;

    static bool attr_done = false;
    if (!attr_done) {
        cudaFuncSetAttribute(mma_gemm<0>, cudaFuncAttributeMaxDynamicSharedMemorySize, SMEM_GEMM);
        cudaFuncSetAttribute(mma_gemm<1>, cudaFuncAttributeMaxDynamicSharedMemorySize, SMEM_GEMM);
        cudaFuncSetAttribute(mma_gemm<2>, cudaFuncAttributeMaxDynamicSharedMemorySize, SMEM_GEMM);
        attr_done = true;
    }

    float *x, *qkv;
    bf16 *xnh, *xnl, *yh, *yl, *hh, *hl;
    bf16 *wqkvh, *wqkvl, *woh, *wol, *w1h, *w1l, *w2h, *w2l, *lmh, *lml;
    cudaGetSymbolAddress((void**)&x,     g_x);
    cudaGetSymbolAddress((void**)&qkv,   g_qkv);
    cudaGetSymbolAddress((void**)&xnh,   g_xn_h);
    cudaGetSymbolAddress((void**)&xnl,   g_xn_l);
    cudaGetSymbolAddress((void**)&yh,    g_y_h);
    cudaGetSymbolAddress((void**)&yl,    g_y_l);
    cudaGetSymbolAddress((void**)&hh,    g_h_h);
    cudaGetSymbolAddress((void**)&hl,    g_h_l);
    cudaGetSymbolAddress((void**)&wqkvh, g_wqkv_h);
    cudaGetSymbolAddress((void**)&wqkvl, g_wqkv_l);
    cudaGetSymbolAddress((void**)&woh,   g_wo_h);
    cudaGetSymbolAddress((void**)&wol,   g_wo_l);
    cudaGetSymbolAddress((void**)&w1h,   g_w1_h);
    cudaGetSymbolAddress((void**)&w1l,   g_w1_l);
    cudaGetSymbolAddress((void**)&w2h,   g_w2_h);
    cudaGetSymbolAddress((void**)&w2l,   g_w2_l);
    cudaGetSymbolAddress((void**)&lmh,   g_lm_h);
    cudaGetSymbolAddress((void**)&lml,   g_lm_l);

    // Launch order chosen so the 6th launch (ncu -s 5 -c 1) is the QKV mma_gemm.
    pack_qkv_kernel<<<4096, 256>>>(wq, wk, wv, wqkvh, wqkvl, (long)NL*NC*C3);  // 1
    split_kernel<<<4096, 256>>>(wo,  woh, wol, (long)NL*NC*NC);                 // 2
    split_kernel<<<8192, 256>>>(w1,  w1h, w1l, (long)NL*NC*NF);                 // 3
    embed_kernel<<<MROWS, 256>>>(idx, tok, pos);                                // 4

    for (int l = 0; l < NL; l++) {
        const long oQ = (long)l * NC * C3;
        const long oO = (long)l * NC * NC;
        const long o1 = (long)l * NC * NF;
        const long o2 = (long)l * NF * NC;

        ln_split_kernel<<<MROWS, 256>>>(x, ln1g + l*NC, ln1b + l*NC, xnh, xnl); // 5 (l=0)
        mma_gemm<0><<<dim3(C3/128, MROWS/128), 256, SMEM_GEMM>>>(
            MROWS, C3, NC, xnh, xnl, wqkvh + oQ, wqkvl + oQ,
            nullptr, nullptr, qkv, nullptr, nullptr);                           // 6 (l=0) <- profiled
        if (l == 0) {
            split_kernel<<<8192, 256>>>(w2,  w2h, w2l, (long)NL*NF*NC);
            split_kernel<<<8192, 256>>>(wlm, lmh, lml, (long)NC*NV);
        }
        attn_kernel<<<dim3(NT, NH, NB), 128>>>(qkv, yh, yl);
        mma_gemm<1><<<dim3(NC/128, MROWS/128), 256, SMEM_GEMM>>>(
            MROWS, NC, NC, yh, yl, woh + oO, wol + oO,
            bo + l*NC, x, x, nullptr, nullptr);
        ln_split_kernel<<<MROWS, 256>>>(x, ln2g + l*NC, ln2b + l*NC, xnh, xnl);
        mma_gemm<2><<<dim3(NF/128, MROWS/128), 256, SMEM_GEMM>>>(
            MROWS, NF, NC, xnh, xnl, w1h + o1, w1l + o1,
            b1 + l*NF, nullptr, nullptr, hh, hl);
        mma_gemm<1><<<dim3(NC/128, MROWS/128), 256, SMEM_GEMM>>>(
            MROWS, NC, NF, hh, hl, w2h + o2, w2l + o2,
            b2 + l*NC, x, x, nullptr, nullptr);
    }

    ln_split_kernel<<<MROWS, 256>>>(x, lnfg, lnfb, xnh, xnl);
    mma_gemm<0><<<dim3(NV/128, MROWS/128), 256, SMEM_GEMM>>>(
        MROWS, NV, NC, xnh, xnl, lmh, lml,
        nullptr, nullptr, out, nullptr, nullptr);
}

// round 8
// speedup vs baseline: 4.1586x; 1.8244x over previous
#include <cuda_runtime.h>
#include <cuda_bf16.h>
#include <math.h>
#include <stdint.h>

#define NL 12
#define NH 16
#define NC 1024
#define NT 512
#define NB 4
#define HDIM 64
#define NF 4096
#define NV 32000
#define MROWS (NB*NT)   // 2048
#define C3 (3*NC)       // 3072
#define LN_EPS 1e-5f

typedef __nv_bfloat16 bf16;
typedef __nv_bfloat162 bf162;

// ---------------- static scratch ----------------
__device__ float g_x   [MROWS*NC];
__device__ float g_qkv [MROWS*C3];
__device__ bf16  g_xn_h[MROWS*NC];
__device__ bf16  g_xn_l[MROWS*NC];
__device__ bf16  g_y_h [MROWS*NC];
__device__ bf16  g_y_l [MROWS*NC];
__device__ bf16  g_h_h [MROWS*NF];
__device__ bf16  g_h_l [MROWS*NF];

// split weights, K-major W[K,N] (as in reference)
__device__ bf16 g_wqkv_h[(long)NL*NC*C3];
__device__ bf16 g_wqkv_l[(long)NL*NC*C3];
__device__ bf16 g_wo_h  [(long)NL*NC*NC];
__device__ bf16 g_wo_l  [(long)NL*NC*NC];
__device__ bf16 g_w1_h  [(long)NL*NC*NF];
__device__ bf16 g_w1_l  [(long)NL*NC*NF];
__device__ bf16 g_w2_h  [(long)NL*NF*NC];
__device__ bf16 g_w2_l  [(long)NL*NF*NC];
__device__ bf16 g_lm_h  [(long)NC*NV];
__device__ bf16 g_lm_l  [(long)NC*NV];

__device__ __forceinline__ void split2(float v, bf16& h, bf16& l) {
    h = __float2bfloat16(v);
    l = __float2bfloat16(v - __bfloat162float(h));
}

// ---------------- conversion kernels ----------------
__global__ void split_kernel(const float* __restrict__ in,
                             bf16* __restrict__ oh, bf16* __restrict__ ol, long n) {
    for (long i = (long)blockIdx.x * blockDim.x + threadIdx.x; i < n;
         i += (long)gridDim.x * blockDim.x) {
        float v = in[i];
        bf16 h, l; split2(v, h, l);
        oh[i] = h; ol[i] = l;
    }
}

__global__ void pack_qkv_kernel(const float* __restrict__ wq,
                                const float* __restrict__ wk,
                                const float* __restrict__ wv,
                                bf16* __restrict__ oh, bf16* __restrict__ ol, long n) {
    for (long i = (long)blockIdx.x * blockDim.x + threadIdx.x; i < n;
         i += (long)gridDim.x * blockDim.x) {
        long lk = i / C3;        // l*NC + k
        int  j  = (int)(i % C3);
        int sel = j >> 10, jj = j & 1023;
        const float* src = (sel == 0) ? wq : (sel == 1) ? wk : wv;
        float v = src[lk * NC + jj];
        bf16 h, l; split2(v, h, l);
        oh[i] = h; ol[i] = l;
    }
}

// ---------------- embedding ----------------
__global__ void embed_kernel(const int* __restrict__ idx,
                             const float* __restrict__ tok,
                             const float* __restrict__ pos) {
    int row = blockIdx.x, t = row % NT;
    int tk = idx[row];
    const float4* tr = (const float4*)(tok + (long)tk * NC);
    const float4* pr = (const float4*)(pos + (long)t  * NC);
    float4* xr = (float4*)(g_x + (long)row * NC);
    for (int c = threadIdx.x; c < NC / 4; c += blockDim.x) {
        float4 a = tr[c], b = pr[c];
        a.x += b.x; a.y += b.y; a.z += b.z; a.w += b.w;
        xr[c] = a;
    }
}

// ---------------- layernorm + split (256 thr/row) ----------------
__global__ __launch_bounds__(256)
void ln_split_kernel(const float* __restrict__ x,
                     const float* __restrict__ gg,
                     const float* __restrict__ bb,
                     bf16* __restrict__ oh, bf16* __restrict__ ol) {
    __shared__ float rs[8], rs2[8];
    const int row = blockIdx.x, tid = threadIdx.x;
    const float4* xr = (const float4*)(x + (long)row * NC);
    float4 v = xr[tid];
    float s  = v.x + v.y + v.z + v.w;
    float s2 = v.x*v.x + v.y*v.y + v.z*v.z + v.w*v.w;
    #pragma unroll
    for (int off = 16; off > 0; off >>= 1) {
        s  += __shfl_xor_sync(0xffffffff, s,  off);
        s2 += __shfl_xor_sync(0xffffffff, s2, off);
    }
    if ((tid & 31) == 0) { rs[tid >> 5] = s; rs2[tid >> 5] = s2; }
    __syncthreads();
    if (tid < 8) {
        s = rs[tid]; s2 = rs2[tid];
        #pragma unroll
        for (int off = 4; off > 0; off >>= 1) {
            s  += __shfl_xor_sync(0xff, s,  off);
            s2 += __shfl_xor_sync(0xff, s2, off);
        }
        if (tid == 0) { rs[0] = s; rs2[0] = s2; }
    }
    __syncthreads();
    float mean = rs[0] * (1.0f / NC);
    float var  = rs2[0] * (1.0f / NC) - mean * mean;
    float rstd = rsqrtf(var + LN_EPS);
    const float4* g4 = (const float4*)gg;
    const float4* b4 = (const float4*)bb;
    float4 g = g4[tid], bv = b4[tid];
    float o0 = (v.x - mean) * rstd * g.x + bv.x;
    float o1 = (v.y - mean) * rstd * g.y + bv.y;
    float o2 = (v.z - mean) * rstd * g.z + bv.z;
    float o3 = (v.w - mean) * rstd * g.w + bv.w;
    bf16 h0,l0,h1,l1,h2,l2,h3,l3;
    split2(o0,h0,l0); split2(o1,h1,l1); split2(o2,h2,l2); split2(o3,h3,l3);
    bf162* oh2 = (bf162*)(oh + (long)row * NC);
    bf162* ol2 = (bf162*)(ol + (long)row * NC);
    oh2[tid*2]   = bf162(h0, h1);
    oh2[tid*2+1] = bf162(h2, h3);
    ol2[tid*2]   = bf162(l0, l1);
    ol2[tid*2+1] = bf162(l2, l3);
}

// ---------------- mma.sync helpers ----------------
__device__ __forceinline__ void ldsm_x4(uint32_t addr, uint32_t& r0, uint32_t& r1,
                                        uint32_t& r2, uint32_t& r3) {
    asm volatile("ldmatrix.sync.aligned.m8n8.x4.shared.b16 {%0,%1,%2,%3},[%4];"
                 : "=r"(r0), "=r"(r1), "=r"(r2), "=r"(r3) : "r"(addr));
}
__device__ __forceinline__ void ldsm_x4_t(uint32_t addr, uint32_t& r0, uint32_t& r1,
                                          uint32_t& r2, uint32_t& r3) {
    asm volatile("ldmatrix.sync.aligned.m8n8.x4.trans.shared.b16 {%0,%1,%2,%3},[%4];"
                 : "=r"(r0), "=r"(r1), "=r"(r2), "=r"(r3) : "r"(addr));
}
__device__ __forceinline__ void mma_bf16(float* c, const uint32_t* a, const uint32_t* b) {
    asm volatile(
        "mma.sync.aligned.m16n8k16.row.col.f32.bf16.bf16.f32 "
        "{%0,%1,%2,%3},{%4,%5,%6,%7},{%8,%9},{%0,%1,%2,%3};"
        : "+f"(c[0]), "+f"(c[1]), "+f"(c[2]), "+f"(c[3])
        : "r"(a[0]), "r"(a[1]), "r"(a[2]), "r"(a[3]), "r"(b[0]), "r"(b[1]));
}
__device__ __forceinline__ void cpa16(uint32_t s, const void* g) {
    asm volatile("cp.async.cg.shared.global [%0],[%1],16;" :: "r"(s), "l"(g));
}

// ---------------- split-bf16 tensor-core GEMM (unchanged from R6) ----------------
#define SMEM_GEMM 65536

template<int EPI>
__global__ __launch_bounds__(256, 2)
void mma_gemm(int M, int N, int K,
              const bf16* __restrict__ Ah, const bf16* __restrict__ Al,
              const bf16* __restrict__ Bh, const bf16* __restrict__ Bl,
              const float* __restrict__ bias, const float* __restrict__ res,
              float* __restrict__ Cf, bf16* __restrict__ Ch, bf16* __restrict__ Cl) {
    extern __shared__ char smem[];
    const uint32_t sbase0 = (uint32_t)__cvta_generic_to_shared(smem);
    const int tid  = threadIdx.x;
    const int lane = tid & 31, warp = tid >> 5;
    const int wm = warp >> 1, wn = warp & 1;        // 4 x 2 warps
    const int m0 = blockIdx.y * 128, n0 = blockIdx.x * 128;
    const int r8 = lane & 7, grp = lane >> 3;
    const int g = lane >> 2, t4 = lane & 3;

    float acc[2][8][4];
    #pragma unroll
    for (int i = 0; i < 2; i++)
        #pragma unroll
        for (int j = 0; j < 8; j++)
            #pragma unroll
            for (int r = 0; r < 4; r++) acc[i][j][r] = 0.f;

    const int T = K >> 5;

    auto load_stage = [&](int stage, int k0) {
        uint32_t sb = sbase0 + stage * 32768;
        #pragma unroll
        for (int it = 0; it < 2; it++) {
            int c = it * 256 + tid;
            int r = c >> 2, cc = c & 3;
            uint32_t so = r * 64 + ((cc ^ ((r >> 1) & 3)) << 4);
            size_t ga = (size_t)(m0 + r) * K + k0 + (cc << 3);
            cpa16(sb +        so, Ah + ga);
            cpa16(sb + 8192 + so, Al + ga);
        }
        #pragma unroll
        for (int it = 0; it < 2; it++) {
            int c = it * 256 + tid;
            int k = c >> 4, nc = c & 15;
            uint32_t so = k * 256 + ((nc ^ (k & 7)) << 4);
            size_t ga = (size_t)(k0 + k) * N + n0 + (nc << 3);
            cpa16(sb + 16384 + so, Bh + ga);
            cpa16(sb + 24576 + so, Bl + ga);
        }
    };

    load_stage(0, 0);
    asm volatile("cp.async.commit_group;");

    for (int t = 0; t < T; t++) {
        if (t + 1 < T) {
            load_stage((t + 1) & 1, (t + 1) << 5);
            asm volatile("cp.async.commit_group;");
            asm volatile("cp.async.wait_group 1;");
        } else {
            asm volatile("cp.async.wait_group 0;");
        }
        __syncthreads();

        uint32_t sA  = sbase0 + (t & 1) * 32768;
        uint32_t sAl = sA + 8192;
        uint32_t sB  = sA + 16384;
        uint32_t sBl = sA + 24576;

        #pragma unroll
        for (int kt = 0; kt < 2; kt++) {
            uint32_t ah[2][4], al_[2][4];
            #pragma unroll
            for (int i = 0; i < 2; i++) {
                int row = wm * 32 + i * 16 + r8 + ((grp & 1) << 3);
                int kc  = kt * 2 + (grp >> 1);
                uint32_t off = row * 64 + ((kc ^ ((row >> 1) & 3)) << 4);
                ldsm_x4(sA  + off, ah[i][0],  ah[i][1],  ah[i][2],  ah[i][3]);
                ldsm_x4(sAl + off, al_[i][0], al_[i][1], al_[i][2], al_[i][3]);
            }
            #pragma unroll
            for (int half = 0; half < 2; half++) {
                uint32_t bh[4][2], bl_[4][2];
                #pragma unroll
                for (int j4 = 0; j4 < 2; j4++) {
                    int k = kt * 16 + r8 + ((grp & 1) << 3);
                    int nch = wn * 8 + (half * 2 + j4) * 2 + (grp >> 1);
                    uint32_t off = k * 256 + ((nch ^ (k & 7)) << 4);
                    ldsm_x4_t(sB  + off, bh[2*j4][0],  bh[2*j4][1],  bh[2*j4+1][0],  bh[2*j4+1][1]);
                    ldsm_x4_t(sBl + off, bl_[2*j4][0], bl_[2*j4][1], bl_[2*j4+1][0], bl_[2*j4+1][1]);
                }
                #pragma unroll
                for (int i = 0; i < 2; i++)
                    #pragma unroll
                    for (int jl = 0; jl < 4; jl++) {
                        float* a = acc[i][half * 4 + jl];
                        mma_bf16(a, ah[i],  bh[jl]);
                        mma_bf16(a, al_[i], bh[jl]);
                        mma_bf16(a, ah[i],  bl_[jl]);
                    }
            }
        }
        __syncthreads();
    }

    #pragma unroll
    for (int i = 0; i < 2; i++) {
        int ra = m0 + wm * 32 + i * 16 + g;
        int rb = ra + 8;
        #pragma unroll
        for (int j = 0; j < 8; j++) {
            int c = n0 + wn * 64 + j * 8 + t4 * 2;
            float v0 = acc[i][j][0], v1 = acc[i][j][1];
            float v2 = acc[i][j][2], v3 = acc[i][j][3];
            if (EPI >= 1) {
                float b0 = bias[c], b1 = bias[c + 1];
                v0 += b0; v1 += b1; v2 += b0; v3 += b1;
            }
            if (EPI == 1) {
                const float2 ra2 = *(const float2*)(res + (size_t)ra * N + c);
                const float2 rb2 = *(const float2*)(res + (size_t)rb * N + c);
                v0 += ra2.x; v1 += ra2.y; v2 += rb2.x; v3 += rb2.y;
            }
            if (EPI <= 1) {
                *(float2*)(Cf + (size_t)ra * N + c) = make_float2(v0, v1);
                *(float2*)(Cf + (size_t)rb * N + c) = make_float2(v2, v3);
            } else {
                v0 = fmaxf(v0, 0.f); v1 = fmaxf(v1, 0.f);
                v2 = fmaxf(v2, 0.f); v3 = fmaxf(v3, 0.f);
                bf16 h0,l0,h1,l1,h2,l2,h3,l3;
                split2(v0,h0,l0); split2(v1,h1,l1);
                split2(v2,h2,l2); split2(v3,h3,l3);
                *(bf162*)(Ch + (size_t)ra * N + c) = bf162(h0, h1);
                *(bf162*)(Ch + (size_t)rb * N + c) = bf162(h2, h3);
                *(bf162*)(Cl + (size_t)ra * N + c) = bf162(l0, l1);
                *(bf162*)(Cl + (size_t)rb * N + c) = bf162(l2, l3);
            }
        }
    }
}

// ---------------- flash attention v3: block = (b, h, 64-query tile) ----------------
// 256 threads as 16(q-groups) x 16(col-groups); thread tile 4x4.
// K/V loaded once per block (L2 traffic /64 vs per-query kernel).
// smem (dynamic): Qs[64][65] d-major | Ks[64][65] d-major | Vs[64][68] s-major |
//                 Ps[64][65] | m[64] l[64] c[64]
#define AQ_PAD 65
#define AV_PAD 68
#define A_QS 0
#define A_KS (64*AQ_PAD)
#define A_VS (A_KS + 64*AQ_PAD)
#define A_PS (A_VS + 64*AV_PAD)
#define A_ST (A_PS + 64*AQ_PAD)
#define SMEM_ATTN ((A_ST + 3*64) * 4)

__global__ __launch_bounds__(256, 2)
void attn_kernel(const float* __restrict__ QKV,
                 bf16* __restrict__ Yh, bf16* __restrict__ Yl) {
    extern __shared__ float sm[];
    float* Qs = sm + A_QS;          // [d][q]
    float* Ks = sm + A_KS;          // [d][s]
    float* Vs = sm + A_VS;          // [s][d]
    float* Ps = sm + A_PS;          // [q][s]
    float* smM = sm + A_ST;
    float* smL = smM + 64;
    float* smC = smL + 64;

    const int qt = (int)(gridDim.x - 1 - blockIdx.x);   // heavy tiles first
    const int h = blockIdx.y, b = blockIdx.z;
    const int tid = threadIdx.x;
    const int qx = tid >> 4, kx = tid & 15;
    const long baseQ = (long)(b * NT) * C3 + h * HDIM;
    const long baseK = baseQ + NC;
    const long baseV = baseQ + 2 * NC;
    const int q0 = qt * 64;

    // load Q tile transposed into Qs[d][q]
    #pragma unroll
    for (int it = 0; it < 4; it++) {
        int i = it * 256 + tid;
        int r = i >> 4, dc = (i & 15) * 4;
        float4 v = *(const float4*)&QKV[baseQ + (long)(q0 + r) * C3 + dc];
        Qs[(dc+0)*AQ_PAD + r] = v.x; Qs[(dc+1)*AQ_PAD + r] = v.y;
        Qs[(dc+2)*AQ_PAD + r] = v.z; Qs[(dc+3)*AQ_PAD + r] = v.w;
    }
    if (tid < 64) { smM[tid] = -1e30f; smL[tid] = 0.f; }

    float O[4][4];
    #pragma unroll
    for (int i = 0; i < 4; i++)
        #pragma unroll
        for (int j = 0; j < 4; j++) O[i][j] = 0.f;
    __syncthreads();

    for (int jt = 0; jt <= qt; jt++) {
        // load K (transposed) and V (row-major) tiles
        #pragma unroll
        for (int it = 0; it < 4; it++) {
            int i = it * 256 + tid;
            int r = i >> 4, dc = (i & 15) * 4;
            float4 v = *(const float4*)&QKV[baseK + (long)(jt * 64 + r) * C3 + dc];
            Ks[(dc+0)*AQ_PAD + r] = v.x; Ks[(dc+1)*AQ_PAD + r] = v.y;
            Ks[(dc+2)*AQ_PAD + r] = v.z; Ks[(dc+3)*AQ_PAD + r] = v.w;
            float4 w = *(const float4*)&QKV[baseV + (long)(jt * 64 + r) * C3 + dc];
            *(float4*)&Vs[r * AV_PAD + dc] = w;
        }
        __syncthreads();

        // S = (Q K^T) * 0.125 : thread -> S[4q][4k]
        float S[4][4];
        #pragma unroll
        for (int i = 0; i < 4; i++)
            #pragma unroll
            for (int j = 0; j < 4; j++) S[i][j] = 0.f;
        #pragma unroll 4
        for (int d = 0; d < 64; d++) {
            float qm[4], kn[4];
            #pragma unroll
            for (int i = 0; i < 4; i++) qm[i] = Qs[d*AQ_PAD + qx*4 + i];
            #pragma unroll
            for (int j = 0; j < 4; j++) kn[j] = Ks[d*AQ_PAD + kx*4 + j];
            #pragma unroll
            for (int i = 0; i < 4; i++)
                #pragma unroll
                for (int j = 0; j < 4; j++) S[i][j] += qm[i] * kn[j];
        }
        const bool diag = (jt == qt);
        #pragma unroll
        for (int i = 0; i < 4; i++)
            #pragma unroll
            for (int j = 0; j < 4; j++) {
                float s = S[i][j] * 0.125f;
                if (diag && (jt*64 + kx*4 + j > q0 + qx*4 + i)) s = -1e30f;
                Ps[(qx*4+i)*AQ_PAD + kx*4 + j] = s;
            }
        __syncthreads();

        // online softmax stats: one owner thread per query row
        if (tid < 64) {
            float mo = smM[tid], rmax = mo;
            #pragma unroll 8
            for (int s = 0; s < 64; s++) rmax = fmaxf(rmax, Ps[tid*AQ_PAD + s]);
            float c = __expf(mo - rmax);
            float rs = 0.f;
            #pragma unroll 8
            for (int s = 0; s < 64; s++) {
                float p = __expf(Ps[tid*AQ_PAD + s] - rmax);
                Ps[tid*AQ_PAD + s] = p;
                rs += p;
            }
            smL[tid] = smL[tid] * c + rs;
            smM[tid] = rmax;
            smC[tid] = c;
        }
        __syncthreads();

        // O = O*c + P @ V : thread -> O[4q][4d], d = kx*4+di
        float cq[4];
        #pragma unroll
        for (int i = 0; i < 4; i++) cq[i] = smC[qx*4 + i];
        #pragma unroll
        for (int i = 0; i < 4; i++)
            #pragma unroll
            for (int j = 0; j < 4; j++) O[i][j] *= cq[i];
        #pragma unroll 4
        for (int s = 0; s < 64; s++) {
            float pv[4], vv[4];
            #pragma unroll
            for (int i = 0; i < 4; i++) pv[i] = Ps[(qx*4+i)*AQ_PAD + s];
            #pragma unroll
            for (int j = 0; j < 4; j++) vv[j] = Vs[s*AV_PAD + kx*4 + j];
            #pragma unroll
            for (int i = 0; i < 4; i++)
                #pragma unroll
                for (int j = 0; j < 4; j++) O[i][j] += pv[i] * vv[j];
        }
        __syncthreads();
    }

    // write y = O / l, split to bf16 hi/lo
    #pragma unroll
    for (int i = 0; i < 4; i++) {
        float inv = 1.0f / smL[qx*4 + i];
        long row = (long)(b * NT + q0 + qx*4 + i);
        long o = row * NC + h * HDIM + kx*4;
        #pragma unroll
        for (int j = 0; j < 4; j += 2) {
            float v0 = O[i][j] * inv, v1 = O[i][j+1] * inv;
            bf16 h0, l0, h1, l1;
            split2(v0, h0, l0); split2(v1, h1, l1);
            *(bf162*)(Yh + o + j) = bf162(h0, h1);
            *(bf162*)(Yl + o + j) = bf162(l0, l1);
        }
    }
}

// ---------------- host driver ----------------
extern "C" void kernel_launch(void* const* d_in, const int* in_sizes, int n_in,
                              void* d_out, int out_size) {
    const int*   idx  = (const int*)  d_in[0];
    const float* tok  = (const float*)d_in[1];
    const float* pos  = (const float*)d_in[2];
    const float* wq   = (const float*)d_in[3];
    const float* wk   = (const float*)d_in[4];
    const float* wv   = (const float*)d_in[5];
    const float* wo   = (const float*)d_in[6];
    const float* bo   = (const float*)d_in[7];
    const float* ln1g = (const float*)d_in[8];
    const float* ln1b = (const float*)d_in[9];
    const float* ln2g = (const float*)d_in[10];
    const float* ln2b = (const float*)d_in[11];
    const float* w1   = (const float*)d_in[12];
    const float* b1   = (const float*)d_in[13];
    const float* w2   = (const float*)d_in[14];
    const float* b2   = (const float*)d_in[15];
    const float* lnfg = (const float*)d_in[16];
    const float* lnfb = (const float*)d_in[17];
    const float* wlm  = (const float*)d_in[18];
    float* out = (float*)d_out;

    static bool attr_done = false;
    if (!attr_done) {
        cudaFuncSetAttribute(mma_gemm<0>, cudaFuncAttributeMaxDynamicSharedMemorySize, SMEM_GEMM);
        cudaFuncSetAttribute(mma_gemm<1>, cudaFuncAttributeMaxDynamicSharedMemorySize, SMEM_GEMM);
        cudaFuncSetAttribute(mma_gemm<2>, cudaFuncAttributeMaxDynamicSharedMemorySize, SMEM_GEMM);
        cudaFuncSetAttribute(attn_kernel, cudaFuncAttributeMaxDynamicSharedMemorySize, SMEM_ATTN);
        attr_done = true;
    }

    float *x, *qkv;
    bf16 *xnh, *xnl, *yh, *yl, *hh, *hl;
    bf16 *wqkvh, *wqkvl, *woh, *wol, *w1h, *w1l, *w2h, *w2l, *lmh, *lml;
    cudaGetSymbolAddress((void**)&x,     g_x);
    cudaGetSymbolAddress((void**)&qkv,   g_qkv);
    cudaGetSymbolAddress((void**)&xnh,   g_xn_h);
    cudaGetSymbolAddress((void**)&xnl,   g_xn_l);
    cudaGetSymbolAddress((void**)&yh,    g_y_h);
    cudaGetSymbolAddress((void**)&yl,    g_y_l);
    cudaGetSymbolAddress((void**)&hh,    g_h_h);
    cudaGetSymbolAddress((void**)&hl,    g_h_l);
    cudaGetSymbolAddress((void**)&wqkvh, g_wqkv_h);
    cudaGetSymbolAddress((void**)&wqkvl, g_wqkv_l);
    cudaGetSymbolAddress((void**)&woh,   g_wo_h);
    cudaGetSymbolAddress((void**)&wol,   g_wo_l);
    cudaGetSymbolAddress((void**)&w1h,   g_w1_h);
    cudaGetSymbolAddress((void**)&w1l,   g_w1_l);
    cudaGetSymbolAddress((void**)&w2h,   g_w2_h);
    cudaGetSymbolAddress((void**)&w2l,   g_w2_l);
    cudaGetSymbolAddress((void**)&lmh,   g_lm_h);
    cudaGetSymbolAddress((void**)&lml,   g_lm_l);

    pack_qkv_kernel<<<4096, 256>>>(wq, wk, wv, wqkvh, wqkvl, (long)NL*NC*C3);
    split_kernel<<<4096, 256>>>(wo,  woh, wol, (long)NL*NC*NC);
    split_kernel<<<8192, 256>>>(w1,  w1h, w1l, (long)NL*NC*NF);
    embed_kernel<<<MROWS, 256>>>(idx, tok, pos);

    for (int l = 0; l < NL; l++) {
        const long oQ = (long)l * NC * C3;
        const long oO = (long)l * NC * NC;
        const long o1 = (long)l * NC * NF;
        const long o2 = (long)l * NF * NC;

        ln_split_kernel<<<MROWS, 256>>>(x, ln1g + l*NC, ln1b + l*NC, xnh, xnl);
        mma_gemm<0><<<dim3(C3/128, MROWS/128), 256, SMEM_GEMM>>>(
            MROWS, C3, NC, xnh, xnl, wqkvh + oQ, wqkvl + oQ,
            nullptr, nullptr, qkv, nullptr, nullptr);
        if (l == 0) {
            split_kernel<<<8192, 256>>>(w2,  w2h, w2l, (long)NL*NF*NC);
            split_kernel<<<8192, 256>>>(wlm, lmh, lml, (long)NC*NV);
        }
        attn_kernel<<<dim3(NT/64, NH, NB), 256, SMEM_ATTN>>>(qkv, yh, yl);
        mma_gemm<1><<<dim3(NC/128, MROWS/128), 256, SMEM_GEMM>>>(
            MROWS, NC, NC, yh, yl, woh + oO, wol + oO,
            bo + l*NC, x, x, nullptr, nullptr);
        ln_split_kernel<<<MROWS, 256>>>(x, ln2g + l*NC, ln2b + l*NC, xnh, xnl);
        mma_gemm<2><<<dim3(NF/128, MROWS/128), 256, SMEM_GEMM>>>(
            MROWS, NF, NC, xnh, xnl, w1h + o1, w1l + o1,
            b1 + l*NF, nullptr, nullptr, hh, hl);
        mma_gemm<1><<<dim3(NC/128, MROWS/128), 256, SMEM_GEMM>>>(
            MROWS, NC, NF, hh, hl, w2h + o2, w2l + o2,
            b2 + l*NC, x, x, nullptr, nullptr);
    }

    ln_split_kernel<<<MROWS, 256>>>(x, lnfg, lnfb, xnh, xnl);
    mma_gemm<0><<<dim3(NV/128, MROWS/128), 256, SMEM_GEMM>>>(
        MROWS, NV, NC, xnh, xnl, lmh, lml,
        nullptr, nullptr, out, nullptr, nullptr);
}